// round 12
// baseline (speedup 1.0000x reference)
#include <cuda_runtime.h>

// Depthwise 3x3 conv, stride 1, VALID, fp32.
// x: (16, 64, 512, 512), w: (64, 3, 3), out: (16, 64, 510, 510).
//
// R8-R10: occupancy + MLP levers saturated; traffic at the 2.14 GB minimum.
// R11: pointer-increment addressing -> 327.7 us, DRAM 84.4%.
// R12 = R11 + load cache policy: main-loop input rows are read-exactly-once
// by this block -> __ldcs (evict-first) so they don't churn L2; the epilogue
// loads (rows y0+30, y0+31) are exactly the halo rows the vertically-adjacent
// block re-reads -> default fill. Stores stay __stcs.

namespace {

constexpr int CH    = 64;
constexpr int H     = 512;
constexpr int W     = 512;
constexpr int OH    = 510;
constexpr int OW    = 510;
constexpr int CHUNK = 30;    // 17 chunks * 30 = 510; multiple of 6
constexpr int TPB   = 128;   // 128 threads * 4 outputs = 512 >= OW

__global__ __launch_bounds__(TPB)
void dwconv3x3_kernel(const float* __restrict__ x,
                      const float* __restrict__ wgt,
                      float* __restrict__ out)
{
    const int plane = blockIdx.y;              // n*CH + c   (slow axis)
    const int c     = plane & (CH - 1);
    const int y0    = blockIdx.x * CHUNK;      // chunk = fast axis -> adjacent
                                               // chunks of a plane co-resident
    const float* wp = wgt + c * 9;
    const float w00 = __ldg(wp + 0), w01 = __ldg(wp + 1), w02 = __ldg(wp + 2);
    const float w10 = __ldg(wp + 3), w11 = __ldg(wp + 4), w12 = __ldg(wp + 5);
    const float w20 = __ldg(wp + 6), w21 = __ldg(wp + 7), w22 = __ldg(wp + 8);

    const int x0   = threadIdx.x * 4;          // 0, 4, ..., 508
    const int lane = threadIdx.x & 31;
    const bool full  = (x0 + 4 <= OW);         // false only for x0 == 508
    const bool halo  = (x0 + 4 < W);           // lane-31 halo load in bounds

    // Base pointers; advanced by 6 rows per iteration so all accesses inside
    // the loop are [reg + constant] (no per-stage address IMADs).
    const float* __restrict__ pin =
        x + (size_t)plane * (H * W) + (size_t)y0 * W + x0;
    float* __restrict__ pout =
        out + (size_t)plane * (OH * OW) + (size_t)y0 * OW + x0;

    // 6-row ring of 6-column strips; fully unrolled -> all registers.
    float r[6][6];

    // Load row (pin + k*W). One float4 per thread; halo cols 4,5 shuffled
    // from lane+1 (its a.x, a.y); lane 31 loads its own float2 halo.
    // stream==true  -> __ldcs (read-once, evict-first; block-private rows)
    // stream==false -> default fill (chunk-boundary halo rows, re-read by
    //                  the vertically-adjacent block via L2).
    auto load_row = [&](float* d, const float* p, int k, bool stream) {
        float4 a;
        if (stream) a = __ldcs(reinterpret_cast<const float4*>(p + k * W));
        else        a = *reinterpret_cast<const float4*>(p + k * W);
        d[0] = a.x; d[1] = a.y; d[2] = a.z; d[3] = a.w;
        d[4] = __shfl_down_sync(0xffffffffu, a.x, 1);
        d[5] = __shfl_down_sync(0xffffffffu, a.y, 1);
        if (lane == 31) {
            if (halo) {
                float2 b;
                if (stream) b = __ldcs(reinterpret_cast<const float2*>(p + k * W + 4));
                else        b = *reinterpret_cast<const float2*>(p + k * W + 4);
                d[4] = b.x; d[5] = b.y;
            } else {
                d[4] = 0.f; d[5] = 0.f;        // x0 == 508: cols 512/513 unused
            }
        }
    };

    // Output row (pout + k*OW) from rows a, b, cc. AL16: byte offset of row
    // y is 2040*y + 4*x0 -> 16B-aligned iff y even; stage parity == row
    // parity (y0 even). Streaming stores keep L2 clean for halo reuse.
    auto proc = [&](const float* a, const float* b, const float* cc,
                    float* p, int k, bool al16) {
        float o[4];
        #pragma unroll
        for (int j = 0; j < 4; ++j) {
            float s;
            s = a[j]      * w00;
            s = fmaf(a[j + 1],  w01, s);
            s = fmaf(a[j + 2],  w02, s);
            s = fmaf(b[j],      w10, s);
            s = fmaf(b[j + 1],  w11, s);
            s = fmaf(b[j + 2],  w12, s);
            s = fmaf(cc[j],     w20, s);
            s = fmaf(cc[j + 1], w21, s);
            s = fmaf(cc[j + 2], w22, s);
            o[j] = s;
        }
        float* orow = p + k * OW;
        if (full) {
            if (al16) {
                __stcs(reinterpret_cast<float4*>(orow),
                       make_float4(o[0], o[1], o[2], o[3]));
            } else {
                __stcs(reinterpret_cast<float2*>(orow),     make_float2(o[0], o[1]));
                __stcs(reinterpret_cast<float2*>(orow) + 1, make_float2(o[2], o[3]));
            }
        } else {                                // x0 == 508: only 508/509 valid
            __stcs(reinterpret_cast<float2*>(orow), make_float2(o[0], o[1]));
        }
    };

    // Prologue: rows y0 .. y0+5. Rows y0, y0+1 may be L2-resident already
    // (they are the previous chunk's halo) — load them with default policy;
    // the rest are private -> streaming.
    load_row(r[0], pin, 0, false);
    load_row(r[1], pin, 1, false);
    load_row(r[2], pin, 2, true );
    load_row(r[3], pin, 3, true );
    load_row(r[4], pin, 4, true );
    load_row(r[5], pin, 5, true );

    // Each iter: 6 output rows + demand-load of the next 6 input rows
    // (load at stage k consumed 4 stages later). All block-private -> __ldcs.
    #pragma unroll 1
    for (int i = 0; i < CHUNK / 6 - 1; ++i) {
        proc(r[0], r[1], r[2], pout, 0, true ); load_row(r[0], pin, 6,  true);
        proc(r[1], r[2], r[3], pout, 1, false); load_row(r[1], pin, 7,  true);
        proc(r[2], r[3], r[4], pout, 2, true ); load_row(r[2], pin, 8,  true);
        proc(r[3], r[4], r[5], pout, 3, false); load_row(r[3], pin, 9,  true);
        proc(r[4], r[5], r[0], pout, 4, true ); load_row(r[4], pin, 10, true);
        proc(r[5], r[0], r[1], pout, 5, false); load_row(r[5], pin, 11, true);
        pin  += 6 * W;
        pout += 6 * OW;
    }

    // Epilogue: rows +6, +7 (= y0+30, y0+31) are EXACTLY the halo rows the
    // next chunk's block re-reads -> default fill so they stay in L2.
    // Last chunk: y0+31 = 511 — in bounds, no clamps.
    proc(r[0], r[1], r[2], pout, 0, true ); load_row(r[0], pin, 6, false);
    proc(r[1], r[2], r[3], pout, 1, false); load_row(r[1], pin, 7, false);
    proc(r[2], r[3], r[4], pout, 2, true );
    proc(r[3], r[4], r[5], pout, 3, false);
    proc(r[4], r[5], r[0], pout, 4, true );
    proc(r[5], r[0], r[1], pout, 5, false);
}

} // namespace

extern "C" void kernel_launch(void* const* d_in, const int* in_sizes, int n_in,
                              void* d_out, int out_size)
{
    const float* x = (const float*)d_in[0];
    const float* w = (const float*)d_in[1];
    float* out     = (float*)d_out;

    const int planes = in_sizes[0] / (H * W);   // 16 * 64 = 1024
    dim3 grid(OH / CHUNK, planes);              // (17, 1024) — chunk fastest
    dwconv3x3_kernel<<<grid, TPB>>>(x, w, out);
}